// round 17
// baseline (speedup 1.0000x reference)
#include <cuda_runtime.h>
#include <cuda_fp16.h>
#include <cstdint>

// Problem constants (N = 262144, D = 64, K = 512)
#define NROWS 262144
#define DIM   64
#define KCB   512

#define THREADS 256
#define TILE_M  256
#define BLOCKS  (NROWS / TILE_M)     // 1024

#define RSCALE     2048.0f           // 2^11: lifts fp16 residuals out of subnormals
#define RSCALE_INV 4.8828125e-4f     // exact 2^-11

// smem layout (bytes)
#define SM_BH   0                    // 512 x 128B
#define SM_BL   65536                // 512 x 128B
#define SM_AH   131072               // 256 x 128B
#define SM_AL   163840               // 256 x 128B
#define SM_W2   196608               // 512 f32
#define SM_X2   198656               // 256 f32
#define SM_RED  199680               // 8 doubles
#define SMEM_BYTES 199744

typedef unsigned long long ull;

// Scratch (static device memory — allocation-free)
__device__ uint8_t  g_wimg[131072];  // swizzled fp16 W image: hi @0, lo(scaled) @65536
__device__ float    g_w2[KCB];
__device__ double   g_partials[BLOCKS];
__device__ unsigned g_ticket;        // zero-init; last CTA resets to 0

// ---- helpers ----
__device__ __forceinline__ uint32_t swz(uint32_t r, uint32_t cbyte) {
    // 128B rows, 8-row XOR swizzle: conflict-free for ldmatrix
    return r * 128u + (cbyte ^ ((r & 7u) << 4));
}
__device__ __forceinline__ uint32_t smem_u32(const void* p) {
    uint32_t a;
    asm("{ .reg .u64 t; cvta.to.shared.u64 t, %1; cvt.u32.u64 %0, t; }"
        : "=r"(a) : "l"(p));
    return a;
}
__device__ __forceinline__ void ldsm4(uint32_t r[4], uint32_t addr) {
    asm volatile("ldmatrix.sync.aligned.m8n8.x4.shared.b16 {%0,%1,%2,%3}, [%4];"
                 : "=r"(r[0]), "=r"(r[1]), "=r"(r[2]), "=r"(r[3]) : "r"(addr));
}
__device__ __forceinline__ void mma16816(float& d0, float& d1, float& d2, float& d3,
                                         const uint32_t* a, uint32_t b0, uint32_t b1) {
    asm volatile("mma.sync.aligned.m16n8k16.row.col.f32.f16.f16.f32 "
                 "{%0,%1,%2,%3}, {%4,%5,%6,%7}, {%8,%9}, {%0,%1,%2,%3};"
                 : "+f"(d0), "+f"(d1), "+f"(d2), "+f"(d3)
                 : "r"(a[0]), "r"(a[1]), "r"(a[2]), "r"(a[3]), "r"(b0), "r"(b1));
}
__device__ __forceinline__ ull umin64(ull a, ull b) { return a < b ? a : b; }

// Convert one fp32 row: stage in regs, ssq in exact sequential order, then
// stores with a per-row j-rotation to kill the 4-way STS bank conflict.
__device__ __forceinline__ float conv_row_f16_rot(const float4* __restrict__ s4,
                                                  char* hi, char* lo, int row,
                                                  int rot) {
    float4 v[16];
    #pragma unroll
    for (int j = 0; j < 16; j++) v[j] = s4[j];

    float ssq = 0.0f;
    #pragma unroll
    for (int j = 0; j < 16; j++) {     // sequential: matches jnp.sum(x*x, axis=1)
        ssq = __fadd_rn(ssq, __fmul_rn(v[j].x, v[j].x));
        ssq = __fadd_rn(ssq, __fmul_rn(v[j].y, v[j].y));
        ssq = __fadd_rn(ssq, __fmul_rn(v[j].z, v[j].z));
        ssq = __fadd_rn(ssq, __fmul_rn(v[j].w, v[j].w));
    }

    #pragma unroll
    for (int jj = 0; jj < 16; jj++) {
        int j = (jj + rot) & 15;       // rotated store order (layout unchanged)
        __half h0 = __float2half_rn(v[j].x), h1 = __float2half_rn(v[j].y);
        __half h2 = __float2half_rn(v[j].z), h3 = __float2half_rn(v[j].w);
        __half l0 = __float2half_rn(__fmul_rn(__fsub_rn(v[j].x, __half2float(h0)), RSCALE));
        __half l1 = __float2half_rn(__fmul_rn(__fsub_rn(v[j].y, __half2float(h1)), RSCALE));
        __half l2 = __float2half_rn(__fmul_rn(__fsub_rn(v[j].z, __half2float(h2)), RSCALE));
        __half l3 = __float2half_rn(__fmul_rn(__fsub_rn(v[j].w, __half2float(h3)), RSCALE));

        uint32_t hA = (uint32_t)__half_as_ushort(h0) | ((uint32_t)__half_as_ushort(h1) << 16);
        uint32_t hB = (uint32_t)__half_as_ushort(h2) | ((uint32_t)__half_as_ushort(h3) << 16);
        uint32_t lA = (uint32_t)__half_as_ushort(l0) | ((uint32_t)__half_as_ushort(l1) << 16);
        uint32_t lB = (uint32_t)__half_as_ushort(l2) | ((uint32_t)__half_as_ushort(l3) << 16);

        uint32_t off = swz((uint32_t)row, (uint32_t)(j * 8));
        *(uint2*)(hi + off) = make_uint2(hA, hB);
        *(uint2*)(lo + off) = make_uint2(lA, lB);
    }
    return ssq;
}

// ============================ Prep: W -> fp16 image + w2 ============================
__global__ __launch_bounds__(128)
void vq_prep(const float* __restrict__ W) {
    const int k = blockIdx.x * 128 + threadIdx.x;
    g_w2[k] = conv_row_f16_rot((const float4*)(W + (size_t)k * DIM),
                               (char*)g_wimg, (char*)g_wimg + 65536, k,
                               ((k >> 3) & 3) * 4);
}

// ============================ Main (fused, B double-buffered) ============================
__global__ __launch_bounds__(THREADS, 1)
void vq_main(const float* __restrict__ enc,
             const float* __restrict__ W,
             float* __restrict__ out) {
    extern __shared__ char sm[];
    const uint32_t sb = smem_u32(sm);
    float* sx2 = (float*)(sm + SM_X2);

    const int tid  = threadIdx.x;
    const int wid  = tid >> 5;
    const int lane = tid & 31;
    const int rowbase = blockIdx.x * TILE_M;

    // Phase 0a: every thread converts one X row (256 rows)
    sx2[tid] = conv_row_f16_rot((const float4*)(enc + (size_t)(rowbase + tid) * DIM),
                                sm + SM_AH, sm + SM_AL, tid,
                                ((tid >> 3) & 3) * 4);
    // Phase 0b: cooperative copy of W image (8192 uint4) + w2
    {
        const uint4* src = (const uint4*)g_wimg;
        uint4*       dst = (uint4*)(sm + SM_BH);
        #pragma unroll
        for (int j = 0; j < 32; j++) dst[tid + j * 256] = src[tid + j * 256];
        ((float*)(sm + SM_W2))[tid]       = g_w2[tid];
        ((float*)(sm + SM_W2))[tid + 256] = g_w2[tid + 256];
    }
    __syncthreads();

    // Phase 1: per-warp MMA over 32 rows (2 groups of 16) x 512 cols
    const int r0 = wid * 32;

    // A fragments: [group][k-step][4 regs], hi and scaled-lo — resident
    uint32_t ah[2][4][4], al[2][4][4];
    {
        const uint32_t cc = (uint32_t)((lane >> 4) << 4);
        #pragma unroll
        for (int g = 0; g < 2; g++) {
            const uint32_t rr = (uint32_t)(r0 + g * 16 + (lane & 15));
            #pragma unroll
            for (int ks = 0; ks < 4; ks++) {
                uint32_t off = swz(rr, (uint32_t)(ks * 32) + cc);
                ldsm4(ah[g][ks], sb + SM_AH + off);
                ldsm4(al[g][ks], sb + SM_AL + off);
            }
        }
    }

    float x2A[2], x2B[2];
    #pragma unroll
    for (int g = 0; g < 2; g++) {
        x2A[g] = sx2[r0 + g * 16 + (lane >> 2)];
        x2B[g] = sx2[r0 + g * 16 + (lane >> 2) + 8];
    }
    const int cix = 2 * (lane & 3);

    ull bestA[2] = {~0ull, ~0ull};
    ull bestB[2] = {~0ull, ~0ull};

    // B addressing: row = t*8 + bn, (row & 7) == bn, so swizzle XOR is
    // loop-invariant. Tile stride = 1024 B.
    const uint32_t bn = (uint32_t)(lane & 7);
    const uint32_t bc = (uint32_t)((lane >> 3) << 4);
    const uint32_t x0 = bc ^ (bn << 4);
    const uint32_t dlt = ((64u + bc) ^ (bn << 4)) - x0;
    const uint32_t pbh0 = sb + SM_BH + bn * 128u + x0;
    const uint32_t pbl0 = pbh0 + 65536u;
    const float* pw2 = (const float*)(sm + SM_W2) + cix;

    // Software pipeline: double-buffered B fragments (hi + scaled-lo)
    uint32_t bhb[2][8], blb[2][8];
    ldsm4(bhb[0],     pbh0);
    ldsm4(bhb[0] + 4, pbh0 + dlt);
    ldsm4(blb[0],     pbl0);
    ldsm4(blb[0] + 4, pbl0 + dlt);

    #pragma unroll 4
    for (int t = 0; t < 64; t++) {
        const int cur = t & 1;
        const int nxt = cur ^ 1;
        // Prefetch tile t+1 (t=63 over-reads into adjacent smem; unused)
        {
            const uint32_t ph = pbh0 + (uint32_t)(t + 1) * 1024u;
            const uint32_t pl = pbl0 + (uint32_t)(t + 1) * 1024u;
            ldsm4(bhb[nxt],     ph);
            ldsm4(bhb[nxt] + 4, ph + dlt);
            ldsm4(blb[nxt],     pl);
            ldsm4(blb[nxt] + 4, pl + dlt);
        }

        const uint32_t* bh = bhb[cur];
        const uint32_t* bl = blb[cur];
        const float2 w2v = *(const float2*)(pw2 + t * 8);
        const int c0 = t * 8 + cix;

        #pragma unroll
        for (int g = 0; g < 2; g++) {
            float uh0 = 0.f, uh1 = 0.f, uh2 = 0.f, uh3 = 0.f;
            float uc0 = 0.f, uc1 = 0.f, uc2 = 0.f, uc3 = 0.f;
            #pragma unroll
            for (int ks = 0; ks < 4; ks++)   // hh: xh . wh
                mma16816(uh0, uh1, uh2, uh3, ah[g][ks], bh[2 * ks], bh[2 * ks + 1]);
            #pragma unroll
            for (int ks = 0; ks < 4; ks++)   // hl: xh . wl'  (scale 2^11)
                mma16816(uc0, uc1, uc2, uc3, ah[g][ks], bl[2 * ks], bl[2 * ks + 1]);
            #pragma unroll
            for (int ks = 0; ks < 4; ks++)   // lh: xl' . wh  (scale 2^11)
                mma16816(uc0, uc1, uc2, uc3, al[g][ks], bh[2 * ks], bh[2 * ks + 1]);

            float dot0 = __fmaf_rn(uc0, RSCALE_INV, uh0);
            float dot1 = __fmaf_rn(uc1, RSCALE_INV, uh1);
            float dot2 = __fmaf_rn(uc2, RSCALE_INV, uh2);
            float dot3 = __fmaf_rn(uc3, RSCALE_INV, uh3);
            // d = fl(fl(x2 - fl(2*dot)) + w2)  — exact reference op order
            // (fl(2*dot) is exact, so fma(dot,-2,x2) gives identical bits)
            float d0 = __fadd_rn(__fmaf_rn(dot0, -2.0f, x2A[g]), w2v.x);
            float d1 = __fadd_rn(__fmaf_rn(dot1, -2.0f, x2A[g]), w2v.y);
            float d2 = __fadd_rn(__fmaf_rn(dot2, -2.0f, x2B[g]), w2v.x);
            float d3 = __fadd_rn(__fmaf_rn(dot3, -2.0f, x2B[g]), w2v.y);
            bestA[g] = umin64(bestA[g], ((ull)__float_as_uint(d0) << 32) | (unsigned)c0);
            bestA[g] = umin64(bestA[g], ((ull)__float_as_uint(d1) << 32) | (unsigned)(c0 + 1));
            bestB[g] = umin64(bestB[g], ((ull)__float_as_uint(d2) << 32) | (unsigned)c0);
            bestB[g] = umin64(bestB[g], ((ull)__float_as_uint(d3) << 32) | (unsigned)(c0 + 1));
        }
    }

    // Cross-lane argmin (lanes sharing a row group); ties -> smaller k
    #pragma unroll
    for (int g = 0; g < 2; g++) {
        bestA[g] = umin64(bestA[g], __shfl_xor_sync(0xFFFFFFFFu, bestA[g], 1));
        bestA[g] = umin64(bestA[g], __shfl_xor_sync(0xFFFFFFFFu, bestA[g], 2));
        bestB[g] = umin64(bestB[g], __shfl_xor_sync(0xFFFFFFFFu, bestB[g], 1));
        bestB[g] = umin64(bestB[g], __shfl_xor_sync(0xFFFFFFFFu, bestB[g], 2));
    }

    // Fused outputs: 4 rows per lane-quad (2 groups x {A, B})
    float s0 = 0.f, s1 = 0.f, s2 = 0.f, s3 = 0.f;
    const int j0 = (lane & 3) * 4;
    #pragma unroll
    for (int g = 0; g < 2; g++) {
        const int rA = rowbase + r0 + g * 16 + (lane >> 2);
        const int rB = rA + 8;
        const int biA = (int)(unsigned)(bestA[g] & 0xFFFFFFFFull);
        const int biB = (int)(unsigned)(bestB[g] & 0xFFFFFFFFull);
        if ((lane & 3) == 0) {
            out[rA] = (float)biA;
            out[rB] = (float)biB;
        }
        #pragma unroll
        for (int r = 0; r < 2; r++) {
            const int row = r ? rB : rA;
            const int bi  = r ? biB : biA;
            const float4* xg = (const float4*)(enc + (size_t)row * DIM);
            const float4* qg = (const float4*)(W + (size_t)bi * DIM);
            float4* o = (float4*)(out + NROWS + (size_t)row * DIM);
            #pragma unroll
            for (int s = 0; s < 4; s++) {
                int j = j0 + s;
                float4 x = xg[j];
                float4 q = __ldg(&qg[j]);
                float d0 = __fsub_rn(q.x, x.x);
                float d1 = __fsub_rn(q.y, x.y);
                float d2 = __fsub_rn(q.z, x.z);
                float d3 = __fsub_rn(q.w, x.w);
                float4 rr;
                rr.x = __fadd_rn(x.x, d0);   // straight-through: fl(x + fl(q - x))
                rr.y = __fadd_rn(x.y, d1);
                rr.z = __fadd_rn(x.z, d2);
                rr.w = __fadd_rn(x.w, d3);
                o[j] = rr;
                s0 = __fmaf_rn(d0, d0, s0);
                s1 = __fmaf_rn(d1, d1, s1);
                s2 = __fmaf_rn(d2, d2, s2);
                s3 = __fmaf_rn(d3, d3, s3);
            }
        }
    }
    double lsum = (double)((s0 + s1) + (s2 + s3));

    // Loss reduction: warp -> CTA -> global ticket
    #pragma unroll
    for (int off = 16; off > 0; off >>= 1)
        lsum += __shfl_xor_sync(0xFFFFFFFFu, lsum, off);

    double* swarp = (double*)(sm + SM_RED);
    __shared__ bool s_last;
    if (lane == 0) swarp[wid] = lsum;
    __syncthreads();

    if (tid == 0) {
        double bsum = 0.0;
        #pragma unroll
        for (int w = 0; w < THREADS / 32; w++) bsum += swarp[w];
        g_partials[blockIdx.x] = bsum;
        __threadfence();
        unsigned old = atomicAdd(&g_ticket, 1u);
        s_last = (old == BLOCKS - 1);
    }
    __syncthreads();

    if (s_last) {
        double t = 0.0;
        for (int i = tid; i < BLOCKS; i += THREADS) t += g_partials[i];
        #pragma unroll
        for (int off = 16; off > 0; off >>= 1)
            t += __shfl_xor_sync(0xFFFFFFFFu, t, off);
        if (lane == 0) swarp[wid] = t;
        __syncthreads();
        if (tid == 0) {
            double tot = 0.0;
            #pragma unroll
            for (int w = 0; w < THREADS / 32; w++) tot += swarp[w];
            float m2 = (float)(tot / (double)((size_t)NROWS * DIM));
            // vq_loss = fl(fl(mean*0.25) + mean)
            out[(size_t)NROWS * (DIM + 1)] = __fadd_rn(__fmul_rn(m2, 0.25f), m2);
            g_ticket = 0;   // deterministic across graph replays
        }
    }
}

extern "C" void kernel_launch(void* const* d_in, const int* in_sizes, int n_in,
                              void* d_out, int out_size) {
    const float* enc = (const float*)d_in[0];   // [N, 64] fp32
    const float* W   = (const float*)d_in[1];   // [512, 64] fp32
    float* out = (float*)d_out;                 // [N | N*64 | 1] fp32

    cudaFuncSetAttribute(vq_main,
                         cudaFuncAttributeMaxDynamicSharedMemorySize, SMEM_BYTES);

    vq_prep<<<KCB / 128, 128>>>(W);
    vq_main<<<BLOCKS, THREADS, SMEM_BYTES>>>(enc, W, out);
}